// round 16
// baseline (speedup 1.0000x reference)
#include <cuda_runtime.h>
#include <cuda_fp16.h>
#include <math.h>
#include <stdint.h>

// ---------------- problem constants ----------------
#define Bb   4
#define Nn   1024
#define Dd   1024
#define Hh   16
#define DH   64
#define MLPd 4096

#define BN_TOK (Bb*Nn)        // 4096 rows
#define MAT    (Bb*Nn*Dd)     // 4M elems

// ---------------- device scratch ----------------
// fp32
__device__ float g_acc [MAT];                  // sa_raw / flash out / ff2 out
__device__ float g_caf [MAT];                  // ca LN output fp32 (residual for final LN)
// fp16 activations
__device__ __half h_qkv [(long)BN_TOK*3*Dd];   // q|k|v, ld 3072
__device__ __half h_vT  [MAT];                 // v transposed per batch
__device__ __half h_attn[MAT];                 // SA dots -> softmax in-place
__device__ __half h_sa  [MAT];                 // SA LN out
__device__ __half h_qc  [MAT];
__device__ __half h_kv  [(long)BN_TOK*2*Dd];   // kc|vc, ld 2048
__device__ __half h_kcT [MAT];                 // kc transposed per batch
__device__ __half h_T   [MAT];                 // T_full
__device__ __half h_ca  [MAT];                 // CA LN out
__device__ __half h_ff  [(long)BN_TOK*MLPd];   // FF hidden
// fp16 inputs/weights (prepared per replay)
__device__ __half h_x   [MAT];
__device__ __half h_e   [MAT];
__device__ __half h_wqkvT[(long)3*Dd*Dd];
__device__ __half h_wcqT [Dd*Dd];
__device__ __half h_wkvT [(long)2*Dd*Dd];
__device__ __half h_w1T  [(long)MLPd*Dd];
__device__ __half h_w2T  [(long)Dd*MLPd];

// ---------------- helpers ----------------
__device__ __forceinline__ uint32_t smem_u32(const void* p) {
    uint32_t a;
    asm("{ .reg .u64 t; cvta.to.shared.u64 t, %1; cvt.u32.u64 %0, t; }" : "=r"(a) : "l"(p));
    return a;
}
#define CP_ASYNC16(dst, src) \
    asm volatile("cp.async.cg.shared.global [%0], [%1], 16;" :: "r"(dst), "l"(src) : "memory")
#define CP_COMMIT() asm volatile("cp.async.commit_group;" ::: "memory")
#define CP_WAIT(n)  asm volatile("cp.async.wait_group %0;" :: "n"(n) : "memory")

__device__ __forceinline__ void ldsm_x4(uint32_t& r0, uint32_t& r1, uint32_t& r2, uint32_t& r3,
                                        uint32_t addr) {
    asm volatile("ldmatrix.sync.aligned.m8n8.x4.shared.b16 {%0,%1,%2,%3}, [%4];"
                 : "=r"(r0), "=r"(r1), "=r"(r2), "=r"(r3) : "r"(addr));
}
__device__ __forceinline__ void mma_f16(float* d, const uint32_t* a, const uint32_t* b) {
    asm volatile(
        "mma.sync.aligned.m16n8k16.row.col.f32.f16.f16.f32 "
        "{%0,%1,%2,%3}, {%4,%5,%6,%7}, {%8,%9}, {%0,%1,%2,%3};"
        : "+f"(d[0]), "+f"(d[1]), "+f"(d[2]), "+f"(d[3])
        : "r"(a[0]), "r"(a[1]), "r"(a[2]), "r"(a[3]), "r"(b[0]), "r"(b[1]));
}
__device__ __forceinline__ float gelu_exact(float x) {
    return 0.5f * x * (1.0f + erff(x * 0.70710678118654752f));
}

// ================= merged prep: cvt + transpose-convert, one launch =================
struct PrepJob { const float* src; __half* dst; int type; int C; int lddst; int roff; int start; };
struct PrepArgs { PrepJob j[10]; };
__global__ void __launch_bounds__(256)
prep_kernel(PrepArgs a)
{
    const int b = blockIdx.x;
    int ji = 0;
    #pragma unroll
    for (int t = 1; t < 10; t++) if (b >= a.j[t].start) ji = t;
    const PrepJob J = a.j[ji];
    const int lb = b - J.start;
    if (J.type == 0) {
        const int idx = lb * 256 + threadIdx.x;
        const float4 v = reinterpret_cast<const float4*>(J.src)[idx];
        __half2* d = reinterpret_cast<__half2*>(J.dst + (long)idx * 4);
        d[0] = __floats2half2_rn(v.x, v.y);
        d[1] = __floats2half2_rn(v.z, v.w);
    } else {
        __shared__ float t[32][33];
        const int nbx = J.C >> 5;
        const int bx = lb % nbx, by = lb / nbx;
        const int r0 = by * 32, c0 = bx * 32;
        const int tx = threadIdx.x & 31, ty = threadIdx.x >> 5;
        #pragma unroll
        for (int i = ty; i < 32; i += 8)
            t[i][tx] = J.src[(long)(r0 + i) * J.C + c0 + tx];
        __syncthreads();
        #pragma unroll
        for (int i = ty; i < 32; i += 8)
            J.dst[(long)(c0 + i + J.roff) * J.lddst + r0 + tx] = __float2half(t[tx][i]);
    }
}

// fp16 [1024][lds] (+coff) -> fp16 transposed [1024][1024], batched (z)
__global__ void __launch_bounds__(256)
tph_kernel(const __half* __restrict__ src, __half* __restrict__ dst,
           int lds, int coff, long sbs)
{
    __shared__ __half t[32][33];
    src += (long)blockIdx.z * sbs;
    dst += (long)blockIdx.z * 1024 * 1024;
    const int r0 = blockIdx.y * 32, c0 = blockIdx.x * 32;
    const int tx = threadIdx.x & 31, ty = threadIdx.x >> 5;
    #pragma unroll
    for (int i = ty; i < 32; i += 8)
        t[i][tx] = src[(long)(r0 + i) * lds + coff + c0 + tx];
    __syncthreads();
    #pragma unroll
    for (int i = ty; i < 32; i += 8)
        dst[(long)(c0 + i) * 1024 + r0 + tx] = t[tx][i];
}

// ================= fp16 mma.sync GEMM (128 thr, 2x2 warps of 64x64, 2 CTA/SM) ======
// C = alpha * A @ B^T; A:[M,K] half (lda), B:[N,K] half (ldb).
// BM=128, BN=128, BK=64 halves. 3-stage cp.async pipeline.
template<bool GELU, bool OUTH>
__global__ void __launch_bounds__(128, 2)
gemm_h(const __half* __restrict__ A, const __half* __restrict__ B, void* __restrict__ Cv,
       const float* __restrict__ bias,
       int K, int lda, int ldb, int ldc,
       long sAb, long sBb, long sCb, float alpha)
{
    constexpr int BM = 128, BK = 64;
    constexpr int SH  = BK + 8;
    constexpr int TSZ = BM * SH;       // 9216 halves per stage tile
    extern __shared__ __half smh[];
    __half* As = smh;
    __half* Bs = smh + 3 * TSZ;
    const uint32_t sAs = smem_u32(As), sBs = smem_u32(Bs);

    const int z = blockIdx.z;
    A += (long)z * sAb;
    B += (long)z * sBb;

    const int tid  = threadIdx.x;
    const int wid  = tid >> 5, lane = tid & 31;
    const int g    = lane >> 2, tig = lane & 3;
    const int m0   = (wid >> 1) * 64;     // 2 M-warps
    const int n0   = (wid & 1) * 64;      // 2 N-warps
    const int rowBase = blockIdx.y * BM;
    const int colBase = blockIdx.x * 128;

    const int lt = lane >> 3, lr = lane & 7;
    uint32_t aOff[4], bOff[4];
    #pragma unroll
    for (int mt = 0; mt < 4; mt++)
        aOff[mt] = (uint32_t)(((m0 + mt * 16 + (lt & 1) * 8 + lr) * 72 + (lt >> 1) * 8) * 2);
    #pragma unroll
    for (int p = 0; p < 4; p++)
        bOff[p] = (uint32_t)(((n0 + p * 16 + (lt >> 1) * 8 + lr) * 72 + (lt & 1) * 8) * 2);

    float acc[4][8][4];
    #pragma unroll
    for (int mt = 0; mt < 4; mt++)
        #pragma unroll
        for (int nt = 0; nt < 8; nt++)
            #pragma unroll
            for (int i = 0; i < 4; i++) acc[mt][nt][i] = 0.0f;

    const int nC = K >> 6;

    auto stage_copy = [&](int s, int k0) {
        // A: 128 rows x 8 chunks (8 halves) = 1024 chunks, 8/thread
        #pragma unroll
        for (int j = 0; j < 8; j++) {
            const int cid = tid + j * 128;
            const int r = cid >> 3, c8 = cid & 7;
            CP_ASYNC16(sAs + (uint32_t)(s * TSZ * 2 + r * 144 + c8 * 16),
                       A + (long)(rowBase + r) * lda + k0 + c8 * 8);
        }
        #pragma unroll
        for (int j = 0; j < 8; j++) {
            const int cid = tid + j * 128;
            const int r = cid >> 3, c8 = cid & 7;
            CP_ASYNC16(sBs + (uint32_t)(s * TSZ * 2 + r * 144 + c8 * 16),
                       B + (long)(colBase + r) * ldb + k0 + c8 * 8);
        }
    };

    auto compute = [&](int s) {
        const uint32_t ab = sAs + (uint32_t)(s * TSZ * 2);
        const uint32_t bb = sBs + (uint32_t)(s * TSZ * 2);
        #pragma unroll
        for (int kk = 0; kk < 4; kk++) {
            uint32_t af[4][4], bf[8][2];
            #pragma unroll
            for (int mt = 0; mt < 4; mt++)
                ldsm_x4(af[mt][0], af[mt][1], af[mt][2], af[mt][3], ab + aOff[mt] + kk * 32);
            #pragma unroll
            for (int p = 0; p < 4; p++)
                ldsm_x4(bf[2*p][0], bf[2*p][1], bf[2*p+1][0], bf[2*p+1][1], bb + bOff[p] + kk * 32);
            #pragma unroll
            for (int mt = 0; mt < 4; mt++)
                #pragma unroll
                for (int nt = 0; nt < 8; nt++)
                    mma_f16(acc[mt][nt], af[mt], bf[nt]);
        }
    };

    stage_copy(0, 0); CP_COMMIT();
    stage_copy(1, BK); CP_COMMIT();
    for (int c = 0; c < nC; c++) {
        if (c + 1 < nC) { CP_WAIT(1); } else { CP_WAIT(0); }
        __syncthreads();
        compute(c % 3);
        if (c + 2 < nC) { stage_copy((c + 2) % 3, (c + 2) * BK); CP_COMMIT(); }
    }

    // epilogue
    #pragma unroll
    for (int mt = 0; mt < 4; mt++) {
        const int r0 = rowBase + m0 + mt * 16 + g;
        #pragma unroll
        for (int nt = 0; nt < 8; nt++) {
            const int cc = colBase + n0 + nt * 8 + 2 * tig;
            float v0 = acc[mt][nt][0], v1 = acc[mt][nt][1];
            float v2 = acc[mt][nt][2], v3 = acc[mt][nt][3];
            if (GELU) {
                const float b0 = bias[cc], b1 = bias[cc + 1];
                v0 = gelu_exact(v0 + b0); v1 = gelu_exact(v1 + b1);
                v2 = gelu_exact(v2 + b0); v3 = gelu_exact(v3 + b1);
            } else {
                v0 *= alpha; v1 *= alpha; v2 *= alpha; v3 *= alpha;
            }
            if (OUTH) {
                __half* C = (__half*)Cv + (long)z * sCb;
                *reinterpret_cast<__half2*>(C + (long)r0 * ldc + cc)       = __floats2half2_rn(v0, v1);
                *reinterpret_cast<__half2*>(C + (long)(r0 + 8) * ldc + cc) = __floats2half2_rn(v2, v3);
            } else {
                float* C = (float*)Cv + (long)z * sCb;
                *reinterpret_cast<float2*>(C + (long)r0 * ldc + cc)       = make_float2(v0, v1);
                *reinterpret_cast<float2*>(C + (long)(r0 + 8) * ldc + cc) = make_float2(v2, v3);
            }
        }
    }
}
#define SGEMM (6 * 128 * 72 * 2)   // 110592 B

// ================= fused CA flash attention (double-buffered K) =================
#define FQ_OFF  0
#define FK0_OFF 9216
#define FK1_OFF 18432
#define FP_OFF  27648
#define FV_OFF  45056
#define FLASH_SMEM ((45056 + 64*136) * 2)   // 107520 B

__global__ void __launch_bounds__(256, 2)
flash_ca(const __half* __restrict__ T, const __half* __restrict__ KC,
         const __half* __restrict__ VC, float* __restrict__ O, int ldkv)
{
    extern __shared__ __half smh[];
    __half* Qs = smh + FQ_OFF;
    __half* Ps = smh + FP_OFF;
    __half* Vt = smh + FV_OFF;
    const uint32_t sQ  = smem_u32(Qs);
    const uint32_t sK0 = smem_u32(smh + FK0_OFF);
    const uint32_t sK1 = smem_u32(smh + FK1_OFF);
    const uint32_t sP  = smem_u32(Ps), sV = smem_u32(Vt);

    const int b = blockIdx.z, h = blockIdx.y;
    const int rowBase = blockIdx.x * 128;
    const __half* Tb = T  + ((long)b * Nn + rowBase) * Dd + h * DH;
    const __half* Kb = KC + (long)b * Nn * ldkv + h * DH;
    const __half* Vb = VC + (long)b * Nn * ldkv + h * DH;
    float* Ob        = O  + ((long)b * Nn + rowBase) * Dd + h * DH;

    const int tid = threadIdx.x;
    const int wid = tid >> 5, lane = tid & 31;
    const int g = lane >> 2, tig = lane & 3;
    const int m0  = (wid >> 2) * 64;
    const int n0  = (wid & 3) * 32;
    const int n0v = (wid & 3) * 16;

    const int lt = lane >> 3, lr = lane & 7;
    uint32_t qOff[4], pOff[4], kOff[2];
    #pragma unroll
    for (int mt = 0; mt < 4; mt++) {
        const int mrow = m0 + mt * 16 + (lt & 1) * 8 + lr;
        qOff[mt] = (uint32_t)((mrow * 72  + (lt >> 1) * 8) * 2);
        pOff[mt] = (uint32_t)((mrow * 136 + (lt >> 1) * 8) * 2);
    }
    #pragma unroll
    for (int p = 0; p < 2; p++)
        kOff[p] = (uint32_t)(((n0 + p * 16 + (lt >> 1) * 8 + lr) * 72 + (lt & 1) * 8) * 2);
    const uint32_t vOff = (uint32_t)(((n0v + (lt >> 1) * 8 + lr) * 136 + (lt & 1) * 8) * 2);

    float accO[4][2][4];
    float den[4][2];
    #pragma unroll
    for (int mt = 0; mt < 4; mt++) {
        den[mt][0] = den[mt][1] = 0.0f;
        #pragma unroll
        for (int nt = 0; nt < 2; nt++)
            #pragma unroll
            for (int i = 0; i < 4; i++) accO[mt][nt][i] = 0.0f;
    }

    auto load_k = [&](uint32_t dstBase, int jt) {
        #pragma unroll
        for (int j = 0; j < 4; j++) {
            const int cid = tid + j * 256;
            const int r = cid >> 3, c8 = cid & 7;
            CP_ASYNC16(dstBase + (uint32_t)(r * 144 + c8 * 16),
                       Kb + (long)(jt * 128 + r) * ldkv + c8 * 8);
        }
    };

    // prologue: G0 = Q + K0; G1 = K1
    #pragma unroll
    for (int j = 0; j < 4; j++) {
        const int cid = tid + j * 256;
        const int r = cid >> 3, c8 = cid & 7;
        CP_ASYNC16(sQ + (uint32_t)(r * 144 + c8 * 16), Tb + (long)r * Dd + c8 * 8);
    }
    load_k(sK0, 0);
    CP_COMMIT();
    load_k(sK1, 1);
    CP_COMMIT();

    const int jrow = tid >> 1;
    const int dhalf = (tid & 1) * 32;

    for (int jt = 0; jt < 8; jt++) {
        const uint32_t sKc = (jt & 1) ? sK1 : sK0;

        uint4 vv[4];
        #pragma unroll
        for (int i = 0; i < 4; i++)
            vv[i] = *reinterpret_cast<const uint4*>(Vb + (long)(jt * 128 + jrow) * ldkv + dhalf + i * 8);

        if (jt < 7) { CP_WAIT(1); } else { CP_WAIT(0); }
        __syncthreads();

        #pragma unroll
        for (int i = 0; i < 4; i++) {
            const __half* hv = reinterpret_cast<const __half*>(&vv[i]);
            #pragma unroll
            for (int e = 0; e < 8; e++)
                Vt[(dhalf + i * 8 + e) * 136 + jrow] = hv[e];
        }

        #pragma unroll
        for (int p = 0; p < 2; p++) {
            float accS[4][2][4];
            #pragma unroll
            for (int mt = 0; mt < 4; mt++)
                #pragma unroll
                for (int nt = 0; nt < 2; nt++)
                    #pragma unroll
                    for (int i = 0; i < 4; i++) accS[mt][nt][i] = 0.0f;
            #pragma unroll
            for (int kk = 0; kk < 4; kk++) {
                uint32_t af[4][4], bf[2][2];
                #pragma unroll
                for (int mt = 0; mt < 4; mt++)
                    ldsm_x4(af[mt][0], af[mt][1], af[mt][2], af[mt][3], sQ + qOff[mt] + kk * 32);
                ldsm_x4(bf[0][0], bf[0][1], bf[1][0], bf[1][1], sKc + kOff[p] + kk * 32);
                #pragma unroll
                for (int mt = 0; mt < 4; mt++)
                    #pragma unroll
                    for (int nt = 0; nt < 2; nt++)
                        mma_f16(accS[mt][nt], af[mt], bf[nt]);
            }
            #pragma unroll
            for (int mt = 0; mt < 4; mt++) {
                const int r0 = m0 + mt * 16 + g;
                #pragma unroll
                for (int nt = 0; nt < 2; nt++) {
                    const int col = n0 + (2 * p + nt) * 8 + 2 * tig;
                    const float e0 = __expf(accS[mt][nt][0] * 0.015625f);
                    const float e1 = __expf(accS[mt][nt][1] * 0.015625f);
                    const float e2 = __expf(accS[mt][nt][2] * 0.015625f);
                    const float e3 = __expf(accS[mt][nt][3] * 0.015625f);
                    den[mt][0] += e0 + e1;
                    den[mt][1] += e2 + e3;
                    *reinterpret_cast<__half2*>(&Ps[r0 * 136 + col])       = __floats2half2_rn(e0, e1);
                    *reinterpret_cast<__half2*>(&Ps[(r0 + 8) * 136 + col]) = __floats2half2_rn(e2, e3);
                }
            }
        }
        __syncthreads();   // P + V^T visible; K[jt] fully consumed

        if (jt + 2 < 8) { load_k(sKc, jt + 2); CP_COMMIT(); }

        #pragma unroll
        for (int kk = 0; kk < 8; kk++) {
            uint32_t af[4][4], bf[2][2];
            #pragma unroll
            for (int mt = 0; mt < 4; mt++)
                ldsm_x4(af[mt][0], af[mt][1], af[mt][2], af[mt][3], sP + pOff[mt] + kk * 32);
            ldsm_x4(bf[0][0], bf[0][1], bf[1][0], bf[1][1], sV + vOff + kk * 32);
            #pragma unroll
            for (int mt = 0; mt < 4; mt++)
                #pragma unroll
                for (int nt = 0; nt < 2; nt++)
                    mma_f16(accO[mt][nt], af[mt], bf[nt]);
        }
        __syncthreads();
    }

    // denominator reduction
    float* Dred = reinterpret_cast<float*>(Ps);
    const int nc = wid & 3;
    #pragma unroll
    for (int mt = 0; mt < 4; mt++) {
        float d0 = den[mt][0], d1 = den[mt][1];
        d0 += __shfl_xor_sync(0xffffffffu, d0, 1); d0 += __shfl_xor_sync(0xffffffffu, d0, 2);
        d1 += __shfl_xor_sync(0xffffffffu, d1, 1); d1 += __shfl_xor_sync(0xffffffffu, d1, 2);
        if (tig == 0) {
            Dred[(m0 + mt * 16 + g) * 4 + nc]     = d0;
            Dred[(m0 + mt * 16 + g + 8) * 4 + nc] = d1;
        }
    }
    __syncthreads();

    #pragma unroll
    for (int mt = 0; mt < 4; mt++) {
        const int r0 = m0 + mt * 16 + g;
        const float4 q0 = *reinterpret_cast<const float4*>(&Dred[r0 * 4]);
        const float4 q1 = *reinterpret_cast<const float4*>(&Dred[(r0 + 8) * 4]);
        const float inv0 = 1.0f / (q0.x + q0.y + q0.z + q0.w);
        const float inv1 = 1.0f / (q1.x + q1.y + q1.z + q1.w);
        #pragma unroll
        for (int nt = 0; nt < 2; nt++) {
            const int col = n0v + nt * 8 + 2 * tig;
            *reinterpret_cast<float2*>(Ob + (long)r0 * Dd + col) =
                make_float2(accO[mt][nt][0] * inv0, accO[mt][nt][1] * inv0);
            *reinterpret_cast<float2*>(Ob + (long)(r0 + 8) * Dd + col) =
                make_float2(accO[mt][nt][2] * inv1, accO[mt][nt][3] * inv1);
        }
    }
}

// ================= row softmax: half in, half out (in-place safe) =================
__global__ void softmax_kernel(__half* __restrict__ X)
{
    long off = (long)blockIdx.x * 1024;
    int tid = threadIdx.x;
    float xv[4];
    float m = -INFINITY;
    #pragma unroll
    for (int i = 0; i < 4; i++) { xv[i] = __half2float(X[off + tid + i*256]); m = fmaxf(m, xv[i]); }

    __shared__ float red[32];
    #pragma unroll
    for (int o = 16; o; o >>= 1) m = fmaxf(m, __shfl_xor_sync(0xffffffffu, m, o));
    if ((tid & 31) == 0) red[tid >> 5] = m;
    __syncthreads();
    if (tid < 32) {
        float v = (tid < 8) ? red[tid] : -INFINITY;
        #pragma unroll
        for (int o = 16; o; o >>= 1) v = fmaxf(v, __shfl_xor_sync(0xffffffffu, v, o));
        if (tid == 0) red[0] = v;
    }
    __syncthreads();
    m = red[0];

    float s = 0.0f;
    #pragma unroll
    for (int i = 0; i < 4; i++) { xv[i] = __expf(xv[i] - m); s += xv[i]; }
    __syncthreads();
    #pragma unroll
    for (int o = 16; o; o >>= 1) s += __shfl_xor_sync(0xffffffffu, s, o);
    if ((tid & 31) == 0) red[tid >> 5] = s;
    __syncthreads();
    if (tid < 32) {
        float v = (tid < 8) ? red[tid] : 0.0f;
        #pragma unroll
        for (int o = 16; o; o >>= 1) v += __shfl_xor_sync(0xffffffffu, v, o);
        if (tid == 0) red[0] = v;
    }
    __syncthreads();
    float inv = 1.0f / red[0];
    #pragma unroll
    for (int i = 0; i < 4; i++) X[off + tid + i*256] = __float2half(xv[i] * inv);
}

// ================= LN(A + R (+ bias)): fp32 and/or half out =================
__global__ void add_ln_kernel(const float* __restrict__ A, const float* __restrict__ R,
                              const float* __restrict__ bias,
                              const float* __restrict__ gamma, const float* __restrict__ beta,
                              float* __restrict__ out_f, __half* __restrict__ out_h)
{
    long off = (long)blockIdx.x * 1024;
    int tid = threadIdx.x;
    float xv[4];
    float s = 0.0f, s2 = 0.0f;
    #pragma unroll
    for (int i = 0; i < 4; i++) {
        int c = tid + i*256;
        float v = A[off + c] + R[off + c];
        if (bias) v += bias[c];
        xv[i] = v; s += v; s2 += v*v;
    }
    __shared__ float rs[32], rs2[32];
    #pragma unroll
    for (int o = 16; o; o >>= 1) { s += __shfl_xor_sync(0xffffffffu, s, o); s2 += __shfl_xor_sync(0xffffffffu, s2, o); }
    if ((tid & 31) == 0) { rs[tid >> 5] = s; rs2[tid >> 5] = s2; }
    __syncthreads();
    if (tid < 32) {
        float a = (tid < 8) ? rs[tid]  : 0.0f;
        float b = (tid < 8) ? rs2[tid] : 0.0f;
        #pragma unroll
        for (int o = 16; o; o >>= 1) { a += __shfl_xor_sync(0xffffffffu, a, o); b += __shfl_xor_sync(0xffffffffu, b, o); }
        if (tid == 0) { rs[0] = a; rs2[0] = b; }
    }
    __syncthreads();
    float mu  = rs[0]  * (1.0f / 1024.0f);
    float var = rs2[0] * (1.0f / 1024.0f) - mu * mu;
    float inv = rsqrtf(var + 1e-5f);
    #pragma unroll
    for (int i = 0; i < 4; i++) {
        int c = tid + i*256;
        float v = (xv[i] - mu) * inv * gamma[c] + beta[c];
        if (out_f) out_f[off + c] = v;
        if (out_h) out_h[off + c] = __float2half(v);
    }
}

// ================= launch =================
extern "C" void kernel_launch(void* const* d_in, const int* in_sizes, int n_in,
                              void* d_out, int out_size)
{
    const float* x      = (const float*)d_in[0];
    const float* enc    = (const float*)d_in[1];
    const float* sa_wq  = (const float*)d_in[2];
    const float* sa_wk  = (const float*)d_in[3];
    const float* sa_wv  = (const float*)d_in[4];
    const float* sa_g   = (const float*)d_in[5];
    const float* sa_b   = (const float*)d_in[6];
    const float* ca_wq  = (const float*)d_in[7];
    const float* ca_wk  = (const float*)d_in[8];
    const float* ca_wv  = (const float*)d_in[9];
    const float* ca_g   = (const float*)d_in[10];
    const float* ca_b   = (const float*)d_in[11];
    const float* w1     = (const float*)d_in[12];
    const float* b1     = (const float*)d_in[13];
    const float* w2     = (const float*)d_in[14];
    const float* b2     = (const float*)d_in[15];
    const float* ff_g   = (const float*)d_in[16];
    const float* ff_b   = (const float*)d_in[17];
    float* out = (float*)d_out;

    float *pacc, *pcaf;
    __half *pqkv, *pvT, *pattn, *psa, *pqc, *pkv, *pkcT, *pT, *pca, *pff;
    __half *px, *pe, *pwqkvT, *pwcqT, *pwkvT, *pw1T, *pw2T;
    cudaGetSymbolAddress((void**)&pacc,  g_acc);
    cudaGetSymbolAddress((void**)&pcaf,  g_caf);
    cudaGetSymbolAddress((void**)&pqkv,  h_qkv);
    cudaGetSymbolAddress((void**)&pvT,   h_vT);
    cudaGetSymbolAddress((void**)&pattn, h_attn);
    cudaGetSymbolAddress((void**)&psa,   h_sa);
    cudaGetSymbolAddress((void**)&pqc,   h_qc);
    cudaGetSymbolAddress((void**)&pkv,   h_kv);
    cudaGetSymbolAddress((void**)&pkcT,  h_kcT);
    cudaGetSymbolAddress((void**)&pT,    h_T);
    cudaGetSymbolAddress((void**)&pca,   h_ca);
    cudaGetSymbolAddress((void**)&pff,   h_ff);
    cudaGetSymbolAddress((void**)&px,    h_x);
    cudaGetSymbolAddress((void**)&pe,    h_e);
    cudaGetSymbolAddress((void**)&pwqkvT, h_wqkvT);
    cudaGetSymbolAddress((void**)&pwcqT,  h_wcqT);
    cudaGetSymbolAddress((void**)&pwkvT,  h_wkvT);
    cudaGetSymbolAddress((void**)&pw1T,   h_w1T);
    cudaGetSymbolAddress((void**)&pw2T,   h_w2T);

    const long MM = (long)Nn * Dd;

    cudaFuncSetAttribute((const void*)gemm_h<false,false>, cudaFuncAttributeMaxDynamicSharedMemorySize, SGEMM);
    cudaFuncSetAttribute((const void*)gemm_h<false,true>,  cudaFuncAttributeMaxDynamicSharedMemorySize, SGEMM);
    cudaFuncSetAttribute((const void*)gemm_h<true,true>,   cudaFuncAttributeMaxDynamicSharedMemorySize, SGEMM);
    cudaFuncSetAttribute((const void*)flash_ca, cudaFuncAttributeMaxDynamicSharedMemorySize, FLASH_SMEM);
    cudaFuncSetAttribute((const void*)gemm_h<false,false>, cudaFuncAttributePreferredSharedMemoryCarveout, 100);
    cudaFuncSetAttribute((const void*)gemm_h<false,true>,  cudaFuncAttributePreferredSharedMemoryCarveout, 100);
    cudaFuncSetAttribute((const void*)gemm_h<true,true>,   cudaFuncAttributePreferredSharedMemoryCarveout, 100);
    cudaFuncSetAttribute((const void*)flash_ca, cudaFuncAttributePreferredSharedMemoryCarveout, 100);

    const dim3 B256(256);
    const dim3 B128(128);

    // ---- merged prep (1 launch) ----
    PrepArgs pa;
    int start = 0;
    auto setjob = [&](int i, const float* s, __half* d, int type, int C, int lddst, int roff, int nblk) {
        pa.j[i].src = s; pa.j[i].dst = d; pa.j[i].type = type;
        pa.j[i].C = C; pa.j[i].lddst = lddst; pa.j[i].roff = roff; pa.j[i].start = start;
        start += nblk;
    };
    setjob(0, x,     px,     0, 0,    0,    0,    MAT/4/256);
    setjob(1, enc,   pe,     0, 0,    0,    0,    MAT/4/256);
    setjob(2, sa_wq, pwqkvT, 1, Dd,   Dd,   0,    1024);
    setjob(3, sa_wk, pwqkvT, 1, Dd,   Dd,   Dd,   1024);
    setjob(4, sa_wv, pwqkvT, 1, Dd,   Dd,   2*Dd, 1024);
    setjob(5, ca_wq, pwcqT,  1, Dd,   Dd,   0,    1024);
    setjob(6, ca_wk, pwkvT,  1, Dd,   Dd,   0,    1024);
    setjob(7, ca_wv, pwkvT,  1, Dd,   Dd,   Dd,   1024);
    setjob(8, w1,    pw1T,   1, MLPd, Dd,   0,    4096);
    setjob(9, w2,    pw2T,   1, Dd,   MLPd, 0,    4096);
    prep_kernel<<<start, B256>>>(pa);

    #define GEMM_F  gemm_h<false,false>
    #define GEMM_H  gemm_h<false,true>
    #define GEMM_GE gemm_h<true,true>

    // ---- Self attention ----
    GEMM_H<<<dim3(24,32,1), B128, SGEMM>>>(px, pwqkvT, pqkv, nullptr, Dd, Dd, Dd, 3*Dd, 0,0,0, 1.0f);
    tph_kernel<<<dim3(32,32,Bb), B256>>>(pqkv, pvT, 3*Dd, 2*Dd, (long)Nn*3*Dd);
    GEMM_H<<<dim3(8,8,Bb), B128, SGEMM>>>(pqkv, pqkv + Dd, pattn, nullptr, Dd, 3*Dd, 3*Dd, Nn,
                                          (long)Nn*3*Dd, (long)Nn*3*Dd, MM, 0.03125f);
    softmax_kernel<<<Bb*Nn, B256>>>(pattn);
    GEMM_F<<<dim3(8,8,Bb), B128, SGEMM>>>(pattn, pvT, pacc, nullptr, Nn, Nn, Nn, Dd,
                                          MM, MM, MM, 1.0f);
    add_ln_kernel<<<BN_TOK, B256>>>(pacc, x, nullptr, sa_g, sa_b, nullptr, psa);

    // ---- Cross attention (kkt folded; flash) ----
    GEMM_H<<<dim3(8,32,1), B128, SGEMM>>>(psa, pwcqT, pqc, nullptr, Dd, Dd, Dd, Dd, 0,0,0, 1.0f);
    GEMM_H<<<dim3(16,32,1), B128, SGEMM>>>(pe, pwkvT, pkv, nullptr, Dd, Dd, Dd, 2*Dd, 0,0,0, 1.0f);
    tph_kernel<<<dim3(32,32,Bb), B256>>>(pkv, pkcT, 2*Dd, 0, (long)Nn*2*Dd);
    GEMM_H<<<dim3(8,8,Bb), B128, SGEMM>>>(pqc, pkcT, pT, nullptr, Dd, Dd, Nn, Dd,
                                          MM, MM, MM, 1.0f);
    flash_ca<<<dim3(8,16,4), B256, FLASH_SMEM>>>(pT, pkv, pkv + Dd, pacc, 2*Dd);
    add_ln_kernel<<<BN_TOK, B256>>>(pacc, enc, nullptr, ca_g, ca_b, pcaf, pca);

    // ---- FeedForward ----
    GEMM_GE<<<dim3(32,32,1), B128, SGEMM>>>(pca, pw1T, pff, b1, Dd, Dd, Dd, MLPd, 0,0,0, 1.0f);
    GEMM_F<<<dim3(8,32,1), B128, SGEMM>>>(pff, pw2T, pacc, nullptr, MLPd, MLPd, MLPd, Dd, 0,0,0, 1.0f);
    add_ln_kernel<<<BN_TOK, B256>>>(pacc, pcaf, b2, ff_g, ff_b, out, nullptr);
}

// round 17
// speedup vs baseline: 1.0570x; 1.0570x over previous
#include <cuda_runtime.h>
#include <cuda_fp16.h>
#include <math.h>
#include <stdint.h>

// ---------------- problem constants ----------------
#define Bb   4
#define Nn   1024
#define Dd   1024
#define Hh   16
#define DH   64
#define MLPd 4096

#define BN_TOK (Bb*Nn)        // 4096 rows
#define MAT    (Bb*Nn*Dd)     // 4M elems

// ---------------- device scratch ----------------
// fp32
__device__ float g_acc [MAT];                  // sa_raw / flash out / ff2 out
__device__ float g_caf [MAT];                  // ca LN output fp32 (residual for final LN)
// fp16 activations
__device__ __half h_qkv [(long)BN_TOK*3*Dd];   // q|k|v, ld 3072
__device__ __half h_vT  [MAT];                 // v transposed per batch
__device__ __half h_attn[MAT];                 // SA dots -> softmax in-place
__device__ __half h_sa  [MAT];                 // SA LN out
__device__ __half h_qc  [MAT];
__device__ __half h_kv  [(long)BN_TOK*2*Dd];   // kc|vc, ld 2048
__device__ __half h_kcT [MAT];                 // kc transposed per batch
__device__ __half h_T   [MAT];                 // T_full
__device__ __half h_ca  [MAT];                 // CA LN out
__device__ __half h_ff  [(long)BN_TOK*MLPd];   // FF hidden
// fp16 inputs/weights (prepared per replay)
__device__ __half h_x   [MAT];
__device__ __half h_e   [MAT];
__device__ __half h_wqkvT[(long)3*Dd*Dd];
__device__ __half h_wcqT [Dd*Dd];
__device__ __half h_wkvT [(long)2*Dd*Dd];
__device__ __half h_w1T  [(long)MLPd*Dd];
__device__ __half h_w2T  [(long)Dd*MLPd];

// ---------------- helpers ----------------
__device__ __forceinline__ uint32_t smem_u32(const void* p) {
    uint32_t a;
    asm("{ .reg .u64 t; cvta.to.shared.u64 t, %1; cvt.u32.u64 %0, t; }" : "=r"(a) : "l"(p));
    return a;
}
#define CP_ASYNC16(dst, src) \
    asm volatile("cp.async.cg.shared.global [%0], [%1], 16;" :: "r"(dst), "l"(src) : "memory")
#define CP_COMMIT() asm volatile("cp.async.commit_group;" ::: "memory")
#define CP_WAIT(n)  asm volatile("cp.async.wait_group %0;" :: "n"(n) : "memory")

__device__ __forceinline__ void ldsm_x4(uint32_t& r0, uint32_t& r1, uint32_t& r2, uint32_t& r3,
                                        uint32_t addr) {
    asm volatile("ldmatrix.sync.aligned.m8n8.x4.shared.b16 {%0,%1,%2,%3}, [%4];"
                 : "=r"(r0), "=r"(r1), "=r"(r2), "=r"(r3) : "r"(addr));
}
__device__ __forceinline__ void mma_f16(float* d, const uint32_t* a, const uint32_t* b) {
    asm volatile(
        "mma.sync.aligned.m16n8k16.row.col.f32.f16.f16.f32 "
        "{%0,%1,%2,%3}, {%4,%5,%6,%7}, {%8,%9}, {%0,%1,%2,%3};"
        : "+f"(d[0]), "+f"(d[1]), "+f"(d[2]), "+f"(d[3])
        : "r"(a[0]), "r"(a[1]), "r"(a[2]), "r"(a[3]), "r"(b[0]), "r"(b[1]));
}
__device__ __forceinline__ float gelu_exact(float x) {
    return 0.5f * x * (1.0f + erff(x * 0.70710678118654752f));
}

// ================= merged prep: cvt + transpose-convert, one launch =================
struct PrepJob { const float* src; __half* dst; int type; int C; int lddst; int roff; int start; };
struct PrepArgs { PrepJob j[10]; };
__global__ void __launch_bounds__(256)
prep_kernel(PrepArgs a)
{
    const int b = blockIdx.x;
    int ji = 0;
    #pragma unroll
    for (int t = 1; t < 10; t++) if (b >= a.j[t].start) ji = t;
    const PrepJob J = a.j[ji];
    const int lb = b - J.start;
    if (J.type == 0) {
        const int idx = lb * 256 + threadIdx.x;
        const float4 v = reinterpret_cast<const float4*>(J.src)[idx];
        __half2* d = reinterpret_cast<__half2*>(J.dst + (long)idx * 4);
        d[0] = __floats2half2_rn(v.x, v.y);
        d[1] = __floats2half2_rn(v.z, v.w);
    } else {
        __shared__ float t[32][33];
        const int nbx = J.C >> 5;
        const int bx = lb % nbx, by = lb / nbx;
        const int r0 = by * 32, c0 = bx * 32;
        const int tx = threadIdx.x & 31, ty = threadIdx.x >> 5;
        #pragma unroll
        for (int i = ty; i < 32; i += 8)
            t[i][tx] = J.src[(long)(r0 + i) * J.C + c0 + tx];
        __syncthreads();
        #pragma unroll
        for (int i = ty; i < 32; i += 8)
            J.dst[(long)(c0 + i + J.roff) * J.lddst + r0 + tx] = __float2half(t[tx][i]);
    }
}

// fp16 [1024][lds] (+coff) -> fp16 transposed [1024][1024], batched (z)
__global__ void __launch_bounds__(256)
tph_kernel(const __half* __restrict__ src, __half* __restrict__ dst,
           int lds, int coff, long sbs)
{
    __shared__ __half t[32][33];
    src += (long)blockIdx.z * sbs;
    dst += (long)blockIdx.z * 1024 * 1024;
    const int r0 = blockIdx.y * 32, c0 = blockIdx.x * 32;
    const int tx = threadIdx.x & 31, ty = threadIdx.x >> 5;
    #pragma unroll
    for (int i = ty; i < 32; i += 8)
        t[i][tx] = src[(long)(r0 + i) * lds + coff + c0 + tx];
    __syncthreads();
    #pragma unroll
    for (int i = ty; i < 32; i += 8)
        dst[(long)(c0 + i) * 1024 + r0 + tx] = t[tx][i];
}

// ================= fp16 mma.sync GEMM (round-13 proven shape) =================
// C = alpha * A @ B^T; A:[M,K] half (lda), B:[N,K] half (ldb).
// BM=128, BN=128, BK=64 halves. 256 threads, 8 warps 2x4, warp tile 64x32.
// 3-stage cp.async pipeline, 2 CTAs/SM.
template<bool GELU, bool OUTH>
__global__ void __launch_bounds__(256, 2)
gemm_h(const __half* __restrict__ A, const __half* __restrict__ B, void* __restrict__ Cv,
       const float* __restrict__ bias,
       int K, int lda, int ldb, int ldc,
       long sAb, long sBb, long sCb, float alpha)
{
    constexpr int BM = 128, BK = 64;
    constexpr int SH  = BK + 8;
    constexpr int TSZ = BM * SH;       // 9216 halves per stage tile
    extern __shared__ __half smh[];
    __half* As = smh;
    __half* Bs = smh + 3 * TSZ;
    const uint32_t sAs = smem_u32(As), sBs = smem_u32(Bs);

    const int z = blockIdx.z;
    A += (long)z * sAb;
    B += (long)z * sBb;

    const int tid  = threadIdx.x;
    const int wid  = tid >> 5, lane = tid & 31;
    const int g    = lane >> 2, tig = lane & 3;
    const int m0   = (wid >> 2) * 64;
    const int n0   = (wid & 3) * 32;
    const int rowBase = blockIdx.y * BM;
    const int colBase = blockIdx.x * 128;

    const int lt = lane >> 3, lr = lane & 7;
    uint32_t aOff[4], bOff[2];
    #pragma unroll
    for (int mt = 0; mt < 4; mt++)
        aOff[mt] = (uint32_t)(((m0 + mt * 16 + (lt & 1) * 8 + lr) * 72 + (lt >> 1) * 8) * 2);
    #pragma unroll
    for (int p = 0; p < 2; p++)
        bOff[p] = (uint32_t)(((n0 + p * 16 + (lt >> 1) * 8 + lr) * 72 + (lt & 1) * 8) * 2);

    float acc[4][4][4];
    #pragma unroll
    for (int mt = 0; mt < 4; mt++)
        #pragma unroll
        for (int nt = 0; nt < 4; nt++)
            #pragma unroll
            for (int i = 0; i < 4; i++) acc[mt][nt][i] = 0.0f;

    const int nC = K >> 6;

    auto stage_copy = [&](int s, int k0) {
        #pragma unroll
        for (int j = 0; j < 4; j++) {
            const int cid = tid + j * 256;
            const int r = cid >> 3, c8 = cid & 7;
            CP_ASYNC16(sAs + (uint32_t)(s * TSZ * 2 + r * 144 + c8 * 16),
                       A + (long)(rowBase + r) * lda + k0 + c8 * 8);
        }
        #pragma unroll
        for (int j = 0; j < 4; j++) {
            const int cid = tid + j * 256;
            const int r = cid >> 3, c8 = cid & 7;
            CP_ASYNC16(sBs + (uint32_t)(s * TSZ * 2 + r * 144 + c8 * 16),
                       B + (long)(colBase + r) * ldb + k0 + c8 * 8);
        }
    };

    auto compute = [&](int s) {
        const uint32_t ab = sAs + (uint32_t)(s * TSZ * 2);
        const uint32_t bb = sBs + (uint32_t)(s * TSZ * 2);
        #pragma unroll
        for (int kk = 0; kk < 4; kk++) {
            uint32_t af[4][4], bf[4][2];
            #pragma unroll
            for (int mt = 0; mt < 4; mt++)
                ldsm_x4(af[mt][0], af[mt][1], af[mt][2], af[mt][3], ab + aOff[mt] + kk * 32);
            #pragma unroll
            for (int p = 0; p < 2; p++)
                ldsm_x4(bf[2*p][0], bf[2*p][1], bf[2*p+1][0], bf[2*p+1][1], bb + bOff[p] + kk * 32);
            #pragma unroll
            for (int mt = 0; mt < 4; mt++)
                #pragma unroll
                for (int nt = 0; nt < 4; nt++)
                    mma_f16(acc[mt][nt], af[mt], bf[nt]);
        }
    };

    stage_copy(0, 0); CP_COMMIT();
    stage_copy(1, BK); CP_COMMIT();
    for (int c = 0; c < nC; c++) {
        if (c + 1 < nC) { CP_WAIT(1); } else { CP_WAIT(0); }
        __syncthreads();
        compute(c % 3);
        if (c + 2 < nC) { stage_copy((c + 2) % 3, (c + 2) * BK); CP_COMMIT(); }
    }

    // epilogue
    #pragma unroll
    for (int mt = 0; mt < 4; mt++) {
        const int r0 = rowBase + m0 + mt * 16 + g;
        #pragma unroll
        for (int nt = 0; nt < 4; nt++) {
            const int cc = colBase + n0 + nt * 8 + 2 * tig;
            float v0 = acc[mt][nt][0], v1 = acc[mt][nt][1];
            float v2 = acc[mt][nt][2], v3 = acc[mt][nt][3];
            if (GELU) {
                const float b0 = bias[cc], b1 = bias[cc + 1];
                v0 = gelu_exact(v0 + b0); v1 = gelu_exact(v1 + b1);
                v2 = gelu_exact(v2 + b0); v3 = gelu_exact(v3 + b1);
            } else {
                v0 *= alpha; v1 *= alpha; v2 *= alpha; v3 *= alpha;
            }
            if (OUTH) {
                __half* C = (__half*)Cv + (long)z * sCb;
                *reinterpret_cast<__half2*>(C + (long)r0 * ldc + cc)       = __floats2half2_rn(v0, v1);
                *reinterpret_cast<__half2*>(C + (long)(r0 + 8) * ldc + cc) = __floats2half2_rn(v2, v3);
            } else {
                float* C = (float*)Cv + (long)z * sCb;
                *reinterpret_cast<float2*>(C + (long)r0 * ldc + cc)       = make_float2(v0, v1);
                *reinterpret_cast<float2*>(C + (long)(r0 + 8) * ldc + cc) = make_float2(v2, v3);
            }
        }
    }
}
#define SGEMM (6 * 128 * 72 * 2)   // 110592 B

// ================= fused CA flash attention (double-buffered K) =================
#define FQ_OFF  0
#define FK0_OFF 9216
#define FK1_OFF 18432
#define FP_OFF  27648
#define FV_OFF  45056
#define FLASH_SMEM ((45056 + 64*136) * 2)   // 107520 B

__global__ void __launch_bounds__(256, 2)
flash_ca(const __half* __restrict__ T, const __half* __restrict__ KC,
         const __half* __restrict__ VC, float* __restrict__ O, int ldkv)
{
    extern __shared__ __half smh[];
    __half* Qs = smh + FQ_OFF;
    __half* Ps = smh + FP_OFF;
    __half* Vt = smh + FV_OFF;
    const uint32_t sQ  = smem_u32(Qs);
    const uint32_t sK0 = smem_u32(smh + FK0_OFF);
    const uint32_t sK1 = smem_u32(smh + FK1_OFF);
    const uint32_t sP  = smem_u32(Ps), sV = smem_u32(Vt);

    const int b = blockIdx.z, h = blockIdx.y;
    const int rowBase = blockIdx.x * 128;
    const __half* Tb = T  + ((long)b * Nn + rowBase) * Dd + h * DH;
    const __half* Kb = KC + (long)b * Nn * ldkv + h * DH;
    const __half* Vb = VC + (long)b * Nn * ldkv + h * DH;
    float* Ob        = O  + ((long)b * Nn + rowBase) * Dd + h * DH;

    const int tid = threadIdx.x;
    const int wid = tid >> 5, lane = tid & 31;
    const int g = lane >> 2, tig = lane & 3;
    const int m0  = (wid >> 2) * 64;
    const int n0  = (wid & 3) * 32;
    const int n0v = (wid & 3) * 16;

    const int lt = lane >> 3, lr = lane & 7;
    uint32_t qOff[4], pOff[4], kOff[2];
    #pragma unroll
    for (int mt = 0; mt < 4; mt++) {
        const int mrow = m0 + mt * 16 + (lt & 1) * 8 + lr;
        qOff[mt] = (uint32_t)((mrow * 72  + (lt >> 1) * 8) * 2);
        pOff[mt] = (uint32_t)((mrow * 136 + (lt >> 1) * 8) * 2);
    }
    #pragma unroll
    for (int p = 0; p < 2; p++)
        kOff[p] = (uint32_t)(((n0 + p * 16 + (lt >> 1) * 8 + lr) * 72 + (lt & 1) * 8) * 2);
    const uint32_t vOff = (uint32_t)(((n0v + (lt >> 1) * 8 + lr) * 136 + (lt & 1) * 8) * 2);

    float accO[4][2][4];
    float den[4][2];
    #pragma unroll
    for (int mt = 0; mt < 4; mt++) {
        den[mt][0] = den[mt][1] = 0.0f;
        #pragma unroll
        for (int nt = 0; nt < 2; nt++)
            #pragma unroll
            for (int i = 0; i < 4; i++) accO[mt][nt][i] = 0.0f;
    }

    auto load_k = [&](uint32_t dstBase, int jt) {
        #pragma unroll
        for (int j = 0; j < 4; j++) {
            const int cid = tid + j * 256;
            const int r = cid >> 3, c8 = cid & 7;
            CP_ASYNC16(dstBase + (uint32_t)(r * 144 + c8 * 16),
                       Kb + (long)(jt * 128 + r) * ldkv + c8 * 8);
        }
    };

    // prologue: G0 = Q + K0; G1 = K1
    #pragma unroll
    for (int j = 0; j < 4; j++) {
        const int cid = tid + j * 256;
        const int r = cid >> 3, c8 = cid & 7;
        CP_ASYNC16(sQ + (uint32_t)(r * 144 + c8 * 16), Tb + (long)r * Dd + c8 * 8);
    }
    load_k(sK0, 0);
    CP_COMMIT();
    load_k(sK1, 1);
    CP_COMMIT();

    const int jrow = tid >> 1;
    const int dhalf = (tid & 1) * 32;

    for (int jt = 0; jt < 8; jt++) {
        const uint32_t sKc = (jt & 1) ? sK1 : sK0;

        uint4 vv[4];
        #pragma unroll
        for (int i = 0; i < 4; i++)
            vv[i] = *reinterpret_cast<const uint4*>(Vb + (long)(jt * 128 + jrow) * ldkv + dhalf + i * 8);

        if (jt < 7) { CP_WAIT(1); } else { CP_WAIT(0); }
        __syncthreads();

        #pragma unroll
        for (int i = 0; i < 4; i++) {
            const __half* hv = reinterpret_cast<const __half*>(&vv[i]);
            #pragma unroll
            for (int e = 0; e < 8; e++)
                Vt[(dhalf + i * 8 + e) * 136 + jrow] = hv[e];
        }

        #pragma unroll
        for (int p = 0; p < 2; p++) {
            float accS[4][2][4];
            #pragma unroll
            for (int mt = 0; mt < 4; mt++)
                #pragma unroll
                for (int nt = 0; nt < 2; nt++)
                    #pragma unroll
                    for (int i = 0; i < 4; i++) accS[mt][nt][i] = 0.0f;
            #pragma unroll
            for (int kk = 0; kk < 4; kk++) {
                uint32_t af[4][4], bf[2][2];
                #pragma unroll
                for (int mt = 0; mt < 4; mt++)
                    ldsm_x4(af[mt][0], af[mt][1], af[mt][2], af[mt][3], sQ + qOff[mt] + kk * 32);
                ldsm_x4(bf[0][0], bf[0][1], bf[1][0], bf[1][1], sKc + kOff[p] + kk * 32);
                #pragma unroll
                for (int mt = 0; mt < 4; mt++)
                    #pragma unroll
                    for (int nt = 0; nt < 2; nt++)
                        mma_f16(accS[mt][nt], af[mt], bf[nt]);
            }
            #pragma unroll
            for (int mt = 0; mt < 4; mt++) {
                const int r0 = m0 + mt * 16 + g;
                #pragma unroll
                for (int nt = 0; nt < 2; nt++) {
                    const int col = n0 + (2 * p + nt) * 8 + 2 * tig;
                    const float e0 = __expf(accS[mt][nt][0] * 0.015625f);
                    const float e1 = __expf(accS[mt][nt][1] * 0.015625f);
                    const float e2 = __expf(accS[mt][nt][2] * 0.015625f);
                    const float e3 = __expf(accS[mt][nt][3] * 0.015625f);
                    den[mt][0] += e0 + e1;
                    den[mt][1] += e2 + e3;
                    *reinterpret_cast<__half2*>(&Ps[r0 * 136 + col])       = __floats2half2_rn(e0, e1);
                    *reinterpret_cast<__half2*>(&Ps[(r0 + 8) * 136 + col]) = __floats2half2_rn(e2, e3);
                }
            }
        }
        __syncthreads();   // P + V^T visible; K[jt] fully consumed

        if (jt + 2 < 8) { load_k(sKc, jt + 2); CP_COMMIT(); }

        #pragma unroll
        for (int kk = 0; kk < 8; kk++) {
            uint32_t af[4][4], bf[2][2];
            #pragma unroll
            for (int mt = 0; mt < 4; mt++)
                ldsm_x4(af[mt][0], af[mt][1], af[mt][2], af[mt][3], sP + pOff[mt] + kk * 32);
            ldsm_x4(bf[0][0], bf[0][1], bf[1][0], bf[1][1], sV + vOff + kk * 32);
            #pragma unroll
            for (int mt = 0; mt < 4; mt++)
                #pragma unroll
                for (int nt = 0; nt < 2; nt++)
                    mma_f16(accO[mt][nt], af[mt], bf[nt]);
        }
        __syncthreads();
    }

    // denominator reduction
    float* Dred = reinterpret_cast<float*>(Ps);
    const int nc = wid & 3;
    #pragma unroll
    for (int mt = 0; mt < 4; mt++) {
        float d0 = den[mt][0], d1 = den[mt][1];
        d0 += __shfl_xor_sync(0xffffffffu, d0, 1); d0 += __shfl_xor_sync(0xffffffffu, d0, 2);
        d1 += __shfl_xor_sync(0xffffffffu, d1, 1); d1 += __shfl_xor_sync(0xffffffffu, d1, 2);
        if (tig == 0) {
            Dred[(m0 + mt * 16 + g) * 4 + nc]     = d0;
            Dred[(m0 + mt * 16 + g + 8) * 4 + nc] = d1;
        }
    }
    __syncthreads();

    #pragma unroll
    for (int mt = 0; mt < 4; mt++) {
        const int r0 = m0 + mt * 16 + g;
        const float4 q0 = *reinterpret_cast<const float4*>(&Dred[r0 * 4]);
        const float4 q1 = *reinterpret_cast<const float4*>(&Dred[(r0 + 8) * 4]);
        const float inv0 = 1.0f / (q0.x + q0.y + q0.z + q0.w);
        const float inv1 = 1.0f / (q1.x + q1.y + q1.z + q1.w);
        #pragma unroll
        for (int nt = 0; nt < 2; nt++) {
            const int col = n0v + nt * 8 + 2 * tig;
            *reinterpret_cast<float2*>(Ob + (long)r0 * Dd + col) =
                make_float2(accO[mt][nt][0] * inv0, accO[mt][nt][1] * inv0);
            *reinterpret_cast<float2*>(Ob + (long)(r0 + 8) * Dd + col) =
                make_float2(accO[mt][nt][2] * inv1, accO[mt][nt][3] * inv1);
        }
    }
}

// ================= row softmax: half in/out, vectorized (4 halves/thread) ==========
__global__ void softmax_kernel(__half* __restrict__ X)
{
    long off = (long)blockIdx.x * 1024;
    int tid = threadIdx.x;
    __half2* X2 = reinterpret_cast<__half2*>(X + off + tid * 4);
    const __half2 a = X2[0], bh = X2[1];
    float xv[4] = { __low2float(a), __high2float(a), __low2float(bh), __high2float(bh) };
    float m = fmaxf(fmaxf(xv[0], xv[1]), fmaxf(xv[2], xv[3]));

    __shared__ float red[32];
    #pragma unroll
    for (int o = 16; o; o >>= 1) m = fmaxf(m, __shfl_xor_sync(0xffffffffu, m, o));
    if ((tid & 31) == 0) red[tid >> 5] = m;
    __syncthreads();
    if (tid < 32) {
        float v = (tid < 8) ? red[tid] : -INFINITY;
        #pragma unroll
        for (int o = 16; o; o >>= 1) v = fmaxf(v, __shfl_xor_sync(0xffffffffu, v, o));
        if (tid == 0) red[0] = v;
    }
    __syncthreads();
    m = red[0];

    float s = 0.0f;
    #pragma unroll
    for (int i = 0; i < 4; i++) { xv[i] = __expf(xv[i] - m); s += xv[i]; }
    __syncthreads();
    #pragma unroll
    for (int o = 16; o; o >>= 1) s += __shfl_xor_sync(0xffffffffu, s, o);
    if ((tid & 31) == 0) red[tid >> 5] = s;
    __syncthreads();
    if (tid < 32) {
        float v = (tid < 8) ? red[tid] : 0.0f;
        #pragma unroll
        for (int o = 16; o; o >>= 1) v += __shfl_xor_sync(0xffffffffu, v, o);
        if (tid == 0) red[0] = v;
    }
    __syncthreads();
    float inv = 1.0f / red[0];
    X2[0] = __floats2half2_rn(xv[0] * inv, xv[1] * inv);
    X2[1] = __floats2half2_rn(xv[2] * inv, xv[3] * inv);
}

// ================= LN(A + R (+ bias)), vectorized float4: fp32 and/or half out =====
__global__ void add_ln_kernel(const float* __restrict__ A, const float* __restrict__ R,
                              const float* __restrict__ bias,
                              const float* __restrict__ gamma, const float* __restrict__ beta,
                              float* __restrict__ out_f, __half* __restrict__ out_h)
{
    long off = (long)blockIdx.x * 1024;
    int tid = threadIdx.x;
    const int c = tid * 4;
    const float4 av = *reinterpret_cast<const float4*>(A + off + c);
    const float4 rv = *reinterpret_cast<const float4*>(R + off + c);
    float4 v = make_float4(av.x + rv.x, av.y + rv.y, av.z + rv.z, av.w + rv.w);
    if (bias) {
        const float4 bv = *reinterpret_cast<const float4*>(bias + c);
        v.x += bv.x; v.y += bv.y; v.z += bv.z; v.w += bv.w;
    }
    float s  = v.x + v.y + v.z + v.w;
    float s2 = v.x * v.x + v.y * v.y + v.z * v.z + v.w * v.w;

    __shared__ float rs[32], rs2[32];
    #pragma unroll
    for (int o = 16; o; o >>= 1) { s += __shfl_xor_sync(0xffffffffu, s, o); s2 += __shfl_xor_sync(0xffffffffu, s2, o); }
    if ((tid & 31) == 0) { rs[tid >> 5] = s; rs2[tid >> 5] = s2; }
    __syncthreads();
    if (tid < 32) {
        float a = (tid < 8) ? rs[tid]  : 0.0f;
        float b = (tid < 8) ? rs2[tid] : 0.0f;
        #pragma unroll
        for (int o = 16; o; o >>= 1) { a += __shfl_xor_sync(0xffffffffu, a, o); b += __shfl_xor_sync(0xffffffffu, b, o); }
        if (tid == 0) { rs[0] = a; rs2[0] = b; }
    }
    __syncthreads();
    const float mu  = rs[0]  * (1.0f / 1024.0f);
    const float var = rs2[0] * (1.0f / 1024.0f) - mu * mu;
    const float inv = rsqrtf(var + 1e-5f);

    const float4 gv = *reinterpret_cast<const float4*>(gamma + c);
    const float4 bv = *reinterpret_cast<const float4*>(beta + c);
    float4 o;
    o.x = (v.x - mu) * inv * gv.x + bv.x;
    o.y = (v.y - mu) * inv * gv.y + bv.y;
    o.z = (v.z - mu) * inv * gv.z + bv.z;
    o.w = (v.w - mu) * inv * gv.w + bv.w;
    if (out_f) *reinterpret_cast<float4*>(out_f + off + c) = o;
    if (out_h) {
        __half2* d = reinterpret_cast<__half2*>(out_h + off + c);
        d[0] = __floats2half2_rn(o.x, o.y);
        d[1] = __floats2half2_rn(o.z, o.w);
    }
}

// ================= launch =================
extern "C" void kernel_launch(void* const* d_in, const int* in_sizes, int n_in,
                              void* d_out, int out_size)
{
    const float* x      = (const float*)d_in[0];
    const float* enc    = (const float*)d_in[1];
    const float* sa_wq  = (const float*)d_in[2];
    const float* sa_wk  = (const float*)d_in[3];
    const float* sa_wv  = (const float*)d_in[4];
    const float* sa_g   = (const float*)d_in[5];
    const float* sa_b   = (const float*)d_in[6];
    const float* ca_wq  = (const float*)d_in[7];
    const float* ca_wk  = (const float*)d_in[8];
    const float* ca_wv  = (const float*)d_in[9];
    const float* ca_g   = (const float*)d_in[10];
    const float* ca_b   = (const float*)d_in[11];
    const float* w1     = (const float*)d_in[12];
    const float* b1     = (const float*)d_in[13];
    const float* w2     = (const float*)d_in[14];
    const float* b2     = (const float*)d_in[15];
    const float* ff_g   = (const float*)d_in[16];
    const float* ff_b   = (const float*)d_in[17];
    float* out = (float*)d_out;

    float *pacc, *pcaf;
    __half *pqkv, *pvT, *pattn, *psa, *pqc, *pkv, *pkcT, *pT, *pca, *pff;
    __half *px, *pe, *pwqkvT, *pwcqT, *pwkvT, *pw1T, *pw2T;
    cudaGetSymbolAddress((void**)&pacc,  g_acc);
    cudaGetSymbolAddress((void**)&pcaf,  g_caf);
    cudaGetSymbolAddress((void**)&pqkv,  h_qkv);
    cudaGetSymbolAddress((void**)&pvT,   h_vT);
    cudaGetSymbolAddress((void**)&pattn, h_attn);
    cudaGetSymbolAddress((void**)&psa,   h_sa);
    cudaGetSymbolAddress((void**)&pqc,   h_qc);
    cudaGetSymbolAddress((void**)&pkv,   h_kv);
    cudaGetSymbolAddress((void**)&pkcT,  h_kcT);
    cudaGetSymbolAddress((void**)&pT,    h_T);
    cudaGetSymbolAddress((void**)&pca,   h_ca);
    cudaGetSymbolAddress((void**)&pff,   h_ff);
    cudaGetSymbolAddress((void**)&px,    h_x);
    cudaGetSymbolAddress((void**)&pe,    h_e);
    cudaGetSymbolAddress((void**)&pwqkvT, h_wqkvT);
    cudaGetSymbolAddress((void**)&pwcqT,  h_wcqT);
    cudaGetSymbolAddress((void**)&pwkvT,  h_wkvT);
    cudaGetSymbolAddress((void**)&pw1T,   h_w1T);
    cudaGetSymbolAddress((void**)&pw2T,   h_w2T);

    const long MM = (long)Nn * Dd;

    cudaFuncSetAttribute((const void*)gemm_h<false,false>, cudaFuncAttributeMaxDynamicSharedMemorySize, SGEMM);
    cudaFuncSetAttribute((const void*)gemm_h<false,true>,  cudaFuncAttributeMaxDynamicSharedMemorySize, SGEMM);
    cudaFuncSetAttribute((const void*)gemm_h<true,true>,   cudaFuncAttributeMaxDynamicSharedMemorySize, SGEMM);
    cudaFuncSetAttribute((const void*)flash_ca, cudaFuncAttributeMaxDynamicSharedMemorySize, FLASH_SMEM);
    cudaFuncSetAttribute((const void*)gemm_h<false,false>, cudaFuncAttributePreferredSharedMemoryCarveout, 100);
    cudaFuncSetAttribute((const void*)gemm_h<false,true>,  cudaFuncAttributePreferredSharedMemoryCarveout, 100);
    cudaFuncSetAttribute((const void*)gemm_h<true,true>,   cudaFuncAttributePreferredSharedMemoryCarveout, 100);
    cudaFuncSetAttribute((const void*)flash_ca, cudaFuncAttributePreferredSharedMemoryCarveout, 100);

    const dim3 B256(256);

    // ---- merged prep (1 launch) ----
    PrepArgs pa;
    int start = 0;
    auto setjob = [&](int i, const float* s, __half* d, int type, int C, int lddst, int roff, int nblk) {
        pa.j[i].src = s; pa.j[i].dst = d; pa.j[i].type = type;
        pa.j[i].C = C; pa.j[i].lddst = lddst; pa.j[i].roff = roff; pa.j[i].start = start;
        start += nblk;
    };
    setjob(0, x,     px,     0, 0,    0,    0,    MAT/4/256);
    setjob(1, enc,   pe,     0, 0,    0,    0,    MAT/4/256);
    setjob(2, sa_wq, pwqkvT, 1, Dd,   Dd,   0,    1024);
    setjob(3, sa_wk, pwqkvT, 1, Dd,   Dd,   Dd,   1024);
    setjob(4, sa_wv, pwqkvT, 1, Dd,   Dd,   2*Dd, 1024);
    setjob(5, ca_wq, pwcqT,  1, Dd,   Dd,   0,    1024);
    setjob(6, ca_wk, pwkvT,  1, Dd,   Dd,   0,    1024);
    setjob(7, ca_wv, pwkvT,  1, Dd,   Dd,   Dd,   1024);
    setjob(8, w1,    pw1T,   1, MLPd, Dd,   0,    4096);
    setjob(9, w2,    pw2T,   1, Dd,   MLPd, 0,    4096);
    prep_kernel<<<start, B256>>>(pa);

    #define GEMM_F  gemm_h<false,false>
    #define GEMM_H  gemm_h<false,true>
    #define GEMM_GE gemm_h<true,true>

    // ---- Self attention ----
    GEMM_H<<<dim3(24,32,1), B256, SGEMM>>>(px, pwqkvT, pqkv, nullptr, Dd, Dd, Dd, 3*Dd, 0,0,0, 1.0f);
    tph_kernel<<<dim3(32,32,Bb), B256>>>(pqkv, pvT, 3*Dd, 2*Dd, (long)Nn*3*Dd);
    GEMM_H<<<dim3(8,8,Bb), B256, SGEMM>>>(pqkv, pqkv + Dd, pattn, nullptr, Dd, 3*Dd, 3*Dd, Nn,
                                          (long)Nn*3*Dd, (long)Nn*3*Dd, MM, 0.03125f);
    softmax_kernel<<<Bb*Nn, B256>>>(pattn);
    GEMM_F<<<dim3(8,8,Bb), B256, SGEMM>>>(pattn, pvT, pacc, nullptr, Nn, Nn, Nn, Dd,
                                          MM, MM, MM, 1.0f);
    add_ln_kernel<<<BN_TOK, B256>>>(pacc, x, nullptr, sa_g, sa_b, nullptr, psa);

    // ---- Cross attention (kkt folded; flash) ----
    GEMM_H<<<dim3(8,32,1), B256, SGEMM>>>(psa, pwcqT, pqc, nullptr, Dd, Dd, Dd, Dd, 0,0,0, 1.0f);
    GEMM_H<<<dim3(16,32,1), B256, SGEMM>>>(pe, pwkvT, pkv, nullptr, Dd, Dd, Dd, 2*Dd, 0,0,0, 1.0f);
    tph_kernel<<<dim3(32,32,Bb), B256>>>(pkv, pkcT, 2*Dd, 0, (long)Nn*2*Dd);
    GEMM_H<<<dim3(8,8,Bb), B256, SGEMM>>>(pqc, pkcT, pT, nullptr, Dd, Dd, Nn, Dd,
                                          MM, MM, MM, 1.0f);
    flash_ca<<<dim3(8,16,4), B256, FLASH_SMEM>>>(pT, pkv, pkv + Dd, pacc, 2*Dd);
    add_ln_kernel<<<BN_TOK, B256>>>(pacc, enc, nullptr, ca_g, ca_b, pcaf, pca);

    // ---- FeedForward ----
    GEMM_GE<<<dim3(32,32,1), B256, SGEMM>>>(pca, pw1T, pff, b1, Dd, Dd, Dd, MLPd, 0,0,0, 1.0f);
    GEMM_F<<<dim3(8,32,1), B256, SGEMM>>>(pff, pw2T, pacc, nullptr, MLPd, MLPd, MLPd, Dd, 0,0,0, 1.0f);
    add_ln_kernel<<<BN_TOK, B256>>>(pacc, pcaf, b2, ff_g, ff_b, out, nullptr);
}